// round 9
// baseline (speedup 1.0000x reference)
#include <cuda_runtime.h>
#include <cstdint>
#include <math.h>

// Problem constants
#define BB 4
#define TT 2048
#define CC 1024
#define HH 16
#define DD 64
#define MROWS (BB * TT)          // 8192
#define C3 (3 * CC)              // 3072

// Scratch (device globals; no allocation allowed)
__device__ float g_qkv[(size_t)MROWS * C3];    // [B*T, 3C]
__device__ float g_attn[(size_t)MROWS * CC];   // [B*T, C]
__device__ float g_wqkv_t[(size_t)C3 * CC];    // W_qkv^T  [3C, C]
__device__ float g_wout_t[(size_t)CC * CC];    // W_out^T  [C, C]

// ---------------------------------------------------------------------------
// tf32 helpers (portable PTX, works on plain sm_103 target)
// ---------------------------------------------------------------------------
__device__ __forceinline__ uint32_t f2tf32(float f) {
    uint32_t r;
    asm("cvt.rna.tf32.f32 %0, %1;" : "=r"(r) : "f"(f));
    return r;
}

__device__ __forceinline__ void mma_tf32_1688(
    float& c0, float& c1, float& c2, float& c3,
    uint32_t a0, uint32_t a1, uint32_t a2, uint32_t a3,
    uint32_t b0, uint32_t b1)
{
    asm volatile(
        "mma.sync.aligned.m16n8k8.row.col.f32.tf32.tf32.f32 "
        "{%0,%1,%2,%3}, {%4,%5,%6,%7}, {%8,%9}, {%0,%1,%2,%3};"
        : "+f"(c0), "+f"(c1), "+f"(c2), "+f"(c3)
        : "r"(a0), "r"(a1), "r"(a2), "r"(a3), "r"(b0), "r"(b1));
}

// ---------------------------------------------------------------------------
// tf32 mma.sync GEMM:  C[M,N] = A[M,K] @ Bt[N,K]^T + bias[N]
// Block 128x256, 256 threads = 8 warps (2x4), warp tile 64x64
// (4 m-tiles x 8 n-tiles of m16n8k8). BK=16 double-buffered.
// Smem stride 20: fragment reads hit banks (20g+tig)&31, all distinct.
// ---------------------------------------------------------------------------
#define GP 20   // floats per smem row (16 + 4)
#define GA_SZ (128 * GP)                 // one A buffer (u32)
#define GB_SZ (256 * GP)                 // one B buffer (u32)
#define GEMM_SMEM ((2 * GA_SZ + 2 * GB_SZ) * 4)   // 61440 bytes

__global__ __launch_bounds__(256, 1) void gemm_mma_tf32(
    const float* __restrict__ A, const float* __restrict__ Bt,
    const float* __restrict__ bias, float* __restrict__ C,
    int M, int N, int K)
{
    extern __shared__ uint32_t gsm[];
    uint32_t* Asm = gsm;               // [2][128*GP]
    uint32_t* Bsm = gsm + 2 * GA_SZ;   // [2][256*GP]

    const int tid = threadIdx.x;
    const int wid = tid >> 5;
    const int lane = tid & 31;
    const int g   = lane >> 2;     // 0..7
    const int tig = lane & 3;      // 0..3

    const int wr = wid >> 2;       // 0..1 -> 64 rows
    const int wc = wid & 3;        // 0..3 -> 64 cols

    const int brow = blockIdx.y * 128;
    const int bcol = blockIdx.x * 256;

    // A loader: row tid>>1 (0..127), 8 cols starting at (tid&1)*8
    const int arow = tid >> 1;
    const int ac8  = (tid & 1) * 8;
    // B loader: row tid (0..255), all 16 cols

    const float* Ab = A + (size_t)brow * K;
    const float* Bb = Bt + (size_t)bcol * K;

    float acc[4][8][4];
    #pragma unroll
    for (int mi = 0; mi < 4; mi++)
        #pragma unroll
        for (int ni = 0; ni < 8; ni++)
            #pragma unroll
            for (int r = 0; r < 4; r++) acc[mi][ni][r] = 0.f;

    const int niter = K / 16;

    // Preload iter 0 into buffer 0
    {
        float4 a0 = *(const float4*)(Ab + (size_t)arow * K + ac8);
        float4 a1 = *(const float4*)(Ab + (size_t)arow * K + ac8 + 4);
        *(uint4*)&Asm[arow * GP + ac8] =
            make_uint4(f2tf32(a0.x), f2tf32(a0.y), f2tf32(a0.z), f2tf32(a0.w));
        *(uint4*)&Asm[arow * GP + ac8 + 4] =
            make_uint4(f2tf32(a1.x), f2tf32(a1.y), f2tf32(a1.z), f2tf32(a1.w));
        #pragma unroll
        for (int j = 0; j < 4; j++) {
            float4 b = *(const float4*)(Bb + (size_t)tid * K + j * 4);
            *(uint4*)&Bsm[tid * GP + j * 4] =
                make_uint4(f2tf32(b.x), f2tf32(b.y), f2tf32(b.z), f2tf32(b.w));
        }
    }
    __syncthreads();

    for (int it = 0; it < niter; it++) {
        const int buf = it & 1;
        const bool has_next = (it + 1) < niter;

        float4 pa0, pa1, pb[4];
        if (has_next) {
            const int k0 = (it + 1) * 16;
            pa0 = *(const float4*)(Ab + (size_t)arow * K + k0 + ac8);
            pa1 = *(const float4*)(Ab + (size_t)arow * K + k0 + ac8 + 4);
            #pragma unroll
            for (int j = 0; j < 4; j++)
                pb[j] = *(const float4*)(Bb + (size_t)tid * K + k0 + j * 4);
        }

        const uint32_t* Ac = Asm + buf * GA_SZ;
        const uint32_t* Bc = Bsm + buf * GB_SZ;

        #pragma unroll
        for (int ks = 0; ks < 2; ks++) {
            const int kb = ks * 8;
            uint32_t af[4][4];
            uint32_t bf[8][2];
            #pragma unroll
            for (int mi = 0; mi < 4; mi++) {
                const int rb = wr * 64 + mi * 16;
                af[mi][0] = Ac[(rb + g) * GP + kb + tig];
                af[mi][1] = Ac[(rb + g + 8) * GP + kb + tig];
                af[mi][2] = Ac[(rb + g) * GP + kb + tig + 4];
                af[mi][3] = Ac[(rb + g + 8) * GP + kb + tig + 4];
            }
            #pragma unroll
            for (int ni = 0; ni < 8; ni++) {
                const int nb = wc * 64 + ni * 8;
                bf[ni][0] = Bc[(nb + g) * GP + kb + tig];
                bf[ni][1] = Bc[(nb + g) * GP + kb + tig + 4];
            }
            #pragma unroll
            for (int mi = 0; mi < 4; mi++)
                #pragma unroll
                for (int ni = 0; ni < 8; ni++)
                    mma_tf32_1688(acc[mi][ni][0], acc[mi][ni][1],
                                  acc[mi][ni][2], acc[mi][ni][3],
                                  af[mi][0], af[mi][1], af[mi][2], af[mi][3],
                                  bf[ni][0], bf[ni][1]);
        }

        if (has_next) {
            uint32_t* An = Asm + (buf ^ 1) * GA_SZ;
            uint32_t* Bn = Bsm + (buf ^ 1) * GB_SZ;
            *(uint4*)&An[arow * GP + ac8] =
                make_uint4(f2tf32(pa0.x), f2tf32(pa0.y), f2tf32(pa0.z), f2tf32(pa0.w));
            *(uint4*)&An[arow * GP + ac8 + 4] =
                make_uint4(f2tf32(pa1.x), f2tf32(pa1.y), f2tf32(pa1.z), f2tf32(pa1.w));
            #pragma unroll
            for (int j = 0; j < 4; j++)
                *(uint4*)&Bn[tid * GP + j * 4] =
                    make_uint4(f2tf32(pb[j].x), f2tf32(pb[j].y),
                               f2tf32(pb[j].z), f2tf32(pb[j].w));
        }
        __syncthreads();
    }

    // Epilogue
    #pragma unroll
    for (int mi = 0; mi < 4; mi++) {
        const int row0 = brow + wr * 64 + mi * 16 + g;
        #pragma unroll
        for (int ni = 0; ni < 8; ni++) {
            const int col0 = bcol + wc * 64 + ni * 8 + 2 * tig;
            const float bx = bias[col0], by = bias[col0 + 1];
            float2 lo = make_float2(acc[mi][ni][0] + bx, acc[mi][ni][1] + by);
            float2 hi = make_float2(acc[mi][ni][2] + bx, acc[mi][ni][3] + by);
            *(float2*)(C + (size_t)row0 * N + col0) = lo;
            *(float2*)(C + (size_t)(row0 + 8) * N + col0) = hi;
        }
    }
}

// ---------------------------------------------------------------------------
// 32x32 tiled transpose
// ---------------------------------------------------------------------------
__global__ void transpose_kernel(const float* __restrict__ W, float* __restrict__ Wt,
                                 int R, int Ccols)
{
    __shared__ float t[32][33];
    int bx = blockIdx.x * 32, by = blockIdx.y * 32;
    int x = bx + threadIdx.x;
    #pragma unroll
    for (int j = 0; j < 32; j += 8)
        t[threadIdx.y + j][threadIdx.x] = W[(size_t)(by + threadIdx.y + j) * Ccols + x];
    __syncthreads();
    int xo = by + threadIdx.x;
    #pragma unroll
    for (int j = 0; j < 32; j += 8)
        Wt[(size_t)(bx + threadIdx.y + j) * R + xo] = t[threadIdx.x][threadIdx.y + j];
}

// ---------------------------------------------------------------------------
// Causal flash attention on tf32 mma.sync (validated R8, unchanged).
// ---------------------------------------------------------------------------
#define AT_PAD 68
#define AT_KS 0
#define AT_VT (64 * AT_PAD)
#define AT_SS (2 * 64 * AT_PAD)
#define ATTN_SMEM ((2 * 64 * AT_PAD + 128 * AT_PAD) * 4)   // 69632 bytes

__global__ __launch_bounds__(256) void attn_mma_kernel(
    const float* __restrict__ qkv, float* __restrict__ out)
{
    extern __shared__ uint32_t sm[];
    uint32_t* Ks = sm + AT_KS;
    uint32_t* Vt = sm + AT_VT;
    uint32_t* Ss = sm + AT_SS;

    const int tid = threadIdx.x;
    const int wid = tid >> 5;
    const int lane = tid & 31;
    const int g = lane >> 2;
    const int tig = lane & 3;
    const int q0 = blockIdx.x * 128;
    const int h = blockIdx.y;
    const int b = blockIdx.z;

    const size_t rs = C3;
    const float* qbase = qkv + (size_t)b * TT * rs + h * DD;
    const float* kbase = qbase + CC;
    const float* vbase = qbase + 2 * CC;

    const int lrow = tid >> 4;        // 0..15
    const int lc4  = (tid & 15) * 4;  // 0..60

    // ---- Stage Q tile (128x64) into Ss as tf32, build A-fragments in regs
    #pragma unroll
    for (int r = 0; r < 8; r++) {
        int row = r * 16 + lrow;
        float4 v = *(const float4*)(qbase + (size_t)(q0 + row) * rs + lc4);
        uint32_t* d = &Ss[row * AT_PAD + lc4];
        d[0] = f2tf32(v.x); d[1] = f2tf32(v.y);
        d[2] = f2tf32(v.z); d[3] = f2tf32(v.w);
    }
    __syncthreads();

    uint32_t qf[8][4];
    {
        const uint32_t* qs = &Ss[(wid * 16) * AT_PAD];
        #pragma unroll
        for (int ks = 0; ks < 8; ks++) {
            qf[ks][0] = qs[g * AT_PAD + ks * 8 + tig];
            qf[ks][1] = qs[(g + 8) * AT_PAD + ks * 8 + tig];
            qf[ks][2] = qs[g * AT_PAD + ks * 8 + tig + 4];
            qf[ks][3] = qs[(g + 8) * AT_PAD + ks * 8 + tig + 4];
        }
    }
    __syncthreads();   // Ss now free for P strips

    float of[8][4];
    #pragma unroll
    for (int nf = 0; nf < 8; nf++)
        #pragma unroll
        for (int r = 0; r < 4; r++) of[nf][r] = 0.f;

    float m_lo = -1e30f, m_hi = -1e30f, l_lo = 0.f, l_hi = 0.f;
    const float sc = 0.125f * 1.44269504088896f;   // scale * log2(e)
    const int nt = q0 / 64 + 2;
    const int qlo = q0 + wid * 16 + g;
    const int qhi = qlo + 8;

    uint32_t* ps = &Ss[(wid * 16) * AT_PAD];   // this warp's P strip

    for (int t = 0; t < nt; t++) {
        const int k0 = t * 64;

        #pragma unroll
        for (int r = 0; r < 4; r++) {
            int row = r * 16 + lrow;
            float4 kv = *(const float4*)(kbase + (size_t)(k0 + row) * rs + lc4);
            uint32_t* kd = &Ks[row * AT_PAD + lc4];
            kd[0] = f2tf32(kv.x); kd[1] = f2tf32(kv.y);
            kd[2] = f2tf32(kv.z); kd[3] = f2tf32(kv.w);
            float4 vv = *(const float4*)(vbase + (size_t)(k0 + row) * rs + lc4);
            float vs[4] = {vv.x, vv.y, vv.z, vv.w};
            #pragma unroll
            for (int i = 0; i < 4; i++) {
                int d = lc4 + i;
                Vt[d * AT_PAD + (row ^ ((d >> 2) & 3))] = f2tf32(vs[i]);
            }
        }
        __syncthreads();

        const bool skip = (t == nt - 1) && (wid < 4);
        if (!skip) {
            float sf[8][4];
            #pragma unroll
            for (int nf = 0; nf < 8; nf++)
                #pragma unroll
                for (int r = 0; r < 4; r++) sf[nf][r] = 0.f;

            #pragma unroll
            for (int ks = 0; ks < 8; ks++) {
                #pragma unroll
                for (int nf = 0; nf < 8; nf++) {
                    uint32_t b0 = Ks[(nf * 8 + g) * AT_PAD + ks * 8 + tig];
                    uint32_t b1 = Ks[(nf * 8 + g) * AT_PAD + ks * 8 + tig + 4];
                    mma_tf32_1688(sf[nf][0], sf[nf][1], sf[nf][2], sf[nf][3],
                                  qf[ks][0], qf[ks][1], qf[ks][2], qf[ks][3],
                                  b0, b1);
                }
            }

            const bool diag = (t == nt - 1) || (t == nt - 2 && wid < 4);
            float tmax_lo = -1e30f, tmax_hi = -1e30f;
            #pragma unroll
            for (int nf = 0; nf < 8; nf++) {
                int kg = k0 + nf * 8 + 2 * tig;
                float s0 = sf[nf][0] * sc, s1 = sf[nf][1] * sc;
                float s2 = sf[nf][2] * sc, s3 = sf[nf][3] * sc;
                if (diag) {
                    if (kg     > qlo) s0 = -1e30f;
                    if (kg + 1 > qlo) s1 = -1e30f;
                    if (kg     > qhi) s2 = -1e30f;
                    if (kg + 1 > qhi) s3 = -1e30f;
                }
                sf[nf][0] = s0; sf[nf][1] = s1; sf[nf][2] = s2; sf[nf][3] = s3;
                tmax_lo = fmaxf(tmax_lo, fmaxf(s0, s1));
                tmax_hi = fmaxf(tmax_hi, fmaxf(s2, s3));
            }
            tmax_lo = fmaxf(tmax_lo, __shfl_xor_sync(0xFFFFFFFFu, tmax_lo, 1));
            tmax_lo = fmaxf(tmax_lo, __shfl_xor_sync(0xFFFFFFFFu, tmax_lo, 2));
            tmax_hi = fmaxf(tmax_hi, __shfl_xor_sync(0xFFFFFFFFu, tmax_hi, 1));
            tmax_hi = fmaxf(tmax_hi, __shfl_xor_sync(0xFFFFFFFFu, tmax_hi, 2));

            const float mn_lo = fmaxf(m_lo, tmax_lo);
            const float mn_hi = fmaxf(m_hi, tmax_hi);
            const float corr_lo = exp2f(m_lo - mn_lo);
            const float corr_hi = exp2f(m_hi - mn_hi);
            m_lo = mn_lo; m_hi = mn_hi;
            l_lo *= corr_lo; l_hi *= corr_hi;
            #pragma unroll
            for (int nf = 0; nf < 8; nf++) {
                of[nf][0] *= corr_lo; of[nf][1] *= corr_lo;
                of[nf][2] *= corr_hi; of[nf][3] *= corr_hi;
            }

            #pragma unroll
            for (int nf = 0; nf < 8; nf++) {
                float p0 = exp2f(sf[nf][0] - mn_lo);
                float p1 = exp2f(sf[nf][1] - mn_lo);
                float p2 = exp2f(sf[nf][2] - mn_hi);
                float p3 = exp2f(sf[nf][3] - mn_hi);
                l_lo += p0 + p1;
                l_hi += p2 + p3;
                uint2 plo = make_uint2(f2tf32(p0), f2tf32(p1));
                uint2 phi = make_uint2(f2tf32(p2), f2tf32(p3));
                *(uint2*)&ps[g * AT_PAD + nf * 8 + 2 * tig] = plo;
                *(uint2*)&ps[(g + 8) * AT_PAD + nf * 8 + 2 * tig] = phi;
            }
            __syncwarp();

            #pragma unroll
            for (int ks = 0; ks < 8; ks++) {
                uint32_t a0 = ps[g * AT_PAD + ks * 8 + tig];
                uint32_t a1 = ps[(g + 8) * AT_PAD + ks * 8 + tig];
                uint32_t a2 = ps[g * AT_PAD + ks * 8 + tig + 4];
                uint32_t a3 = ps[(g + 8) * AT_PAD + ks * 8 + tig + 4];
                #pragma unroll
                for (int nf = 0; nf < 8; nf++) {
                    int drow = nf * 8 + g;
                    int f = (drow >> 2) & 3;
                    uint32_t b0 = Vt[drow * AT_PAD + ((ks * 8 + tig) ^ f)];
                    uint32_t b1 = Vt[drow * AT_PAD + ((ks * 8 + tig + 4) ^ f)];
                    mma_tf32_1688(of[nf][0], of[nf][1], of[nf][2], of[nf][3],
                                  a0, a1, a2, a3, b0, b1);
                }
            }
        }
        __syncthreads();
    }

    l_lo += __shfl_xor_sync(0xFFFFFFFFu, l_lo, 1);
    l_lo += __shfl_xor_sync(0xFFFFFFFFu, l_lo, 2);
    l_hi += __shfl_xor_sync(0xFFFFFFFFu, l_hi, 1);
    l_hi += __shfl_xor_sync(0xFFFFFFFFu, l_hi, 2);
    const float inv_lo = 1.f / l_lo;
    const float inv_hi = 1.f / l_hi;

    float* olo = out + ((size_t)b * TT + qlo) * CC + h * DD;
    float* ohi = out + ((size_t)b * TT + qhi) * CC + h * DD;
    #pragma unroll
    for (int nf = 0; nf < 8; nf++) {
        float2 lo = make_float2(of[nf][0] * inv_lo, of[nf][1] * inv_lo);
        float2 hi = make_float2(of[nf][2] * inv_hi, of[nf][3] * inv_hi);
        *(float2*)(olo + nf * 8 + 2 * tig) = lo;
        *(float2*)(ohi + nf * 8 + 2 * tig) = hi;
    }
}

// ---------------------------------------------------------------------------
// Launch
// ---------------------------------------------------------------------------
extern "C" void kernel_launch(void* const* d_in, const int* in_sizes, int n_in,
                              void* d_out, int out_size)
{
    const float* x     = (const float*)d_in[0];
    const float* W_qkv = (const float*)d_in[1];
    const float* b_qkv = (const float*)d_in[2];
    const float* W_out = (const float*)d_in[3];
    const float* b_out = (const float*)d_in[4];
    float* out = (float*)d_out;

    float *qkv = nullptr, *attn = nullptr, *wqkv_t = nullptr, *wout_t = nullptr;
    cudaGetSymbolAddress((void**)&qkv,    g_qkv);
    cudaGetSymbolAddress((void**)&attn,   g_attn);
    cudaGetSymbolAddress((void**)&wqkv_t, g_wqkv_t);
    cudaGetSymbolAddress((void**)&wout_t, g_wout_t);

    cudaFuncSetAttribute(gemm_mma_tf32,
                         cudaFuncAttributeMaxDynamicSharedMemorySize, GEMM_SMEM);
    cudaFuncSetAttribute(attn_mma_kernel,
                         cudaFuncAttributeMaxDynamicSharedMemorySize, ATTN_SMEM);

    // 0) Transpose weights to K-major
    {
        dim3 blk(32, 8);
        transpose_kernel<<<dim3(C3 / 32, CC / 32), blk>>>(W_qkv, wqkv_t, CC, C3);
        transpose_kernel<<<dim3(CC / 32, CC / 32), blk>>>(W_out, wout_t, CC, CC);
    }

    // 1) QKV projection (tf32 mma.sync, 128x256 blocks)
    {
        dim3 grid(C3 / 256, MROWS / 128);
        gemm_mma_tf32<<<grid, 256, GEMM_SMEM>>>(x, wqkv_t, b_qkv, qkv, MROWS, C3, CC);
    }

    // 2) Causal attention (tf32 mma.sync flash attention)
    {
        dim3 grid(TT / 128, HH, BB);
        attn_mma_kernel<<<grid, 256, ATTN_SMEM>>>(qkv, attn);
    }

    // 3) Output projection (tf32 mma.sync, 128x256 blocks)
    {
        dim3 grid(CC / 256, MROWS / 128);
        gemm_mma_tf32<<<grid, 256, GEMM_SMEM>>>(attn, wout_t, b_out, out, MROWS, CC, CC);
    }
}

// round 10
// speedup vs baseline: 1.3872x; 1.3872x over previous
#include <cuda_runtime.h>
#include <cstdint>
#include <math.h>

// Problem constants
#define BB 4
#define TT 2048
#define CC 1024
#define HH 16
#define DD 64
#define MROWS (BB * TT)          // 8192
#define C3 (3 * CC)              // 3072

// Scratch (device globals; no allocation allowed)
__device__ float g_qkv[(size_t)MROWS * C3];    // [B*T, 3C]
__device__ float g_attn[(size_t)MROWS * CC];   // [B*T, C]
__device__ float g_wqkv_t[(size_t)C3 * CC];    // W_qkv^T  [3C, C]
__device__ float g_wout_t[(size_t)CC * CC];    // W_out^T  [C, C]

// ---------------------------------------------------------------------------
// tf32 + ldmatrix helpers (portable PTX, plain sm_103 target)
// ---------------------------------------------------------------------------
__device__ __forceinline__ uint32_t f2tf32(float f) {
    uint32_t r;
    asm("cvt.rna.tf32.f32 %0, %1;" : "=r"(r) : "f"(f));
    return r;
}

__device__ __forceinline__ uint32_t smem_u32(const void* p) {
    uint32_t a;
    asm("{ .reg .u64 t; cvta.to.shared.u64 t, %1; cvt.u32.u64 %0, t; }"
        : "=r"(a) : "l"(p));
    return a;
}

__device__ __forceinline__ void ldsm_x4(uint32_t& r0, uint32_t& r1,
                                        uint32_t& r2, uint32_t& r3,
                                        uint32_t saddr) {
    asm volatile("ldmatrix.sync.aligned.m8n8.x4.shared.b16 {%0,%1,%2,%3}, [%4];"
                 : "=r"(r0), "=r"(r1), "=r"(r2), "=r"(r3) : "r"(saddr));
}

__device__ __forceinline__ void mma_tf32_1688(
    float& c0, float& c1, float& c2, float& c3,
    uint32_t a0, uint32_t a1, uint32_t a2, uint32_t a3,
    uint32_t b0, uint32_t b1)
{
    asm volatile(
        "mma.sync.aligned.m16n8k8.row.col.f32.tf32.tf32.f32 "
        "{%0,%1,%2,%3}, {%4,%5,%6,%7}, {%8,%9}, {%0,%1,%2,%3};"
        : "+f"(c0), "+f"(c1), "+f"(c2), "+f"(c3)
        : "r"(a0), "r"(a1), "r"(a2), "r"(a3), "r"(b0), "r"(b1));
}

// ---------------------------------------------------------------------------
// tf32 mma.sync GEMM (R8 shape: block 128x128, 8 warps, warp tile 64x32,
// BK=16 double-buffered, stride-20 smem) with ldmatrix fragment loads.
// ---------------------------------------------------------------------------
#define PAD 20   // floats per smem row (16 + 4)
#define GA (128 * PAD)

__global__ __launch_bounds__(256) void gemm_mma_tf32(
    const float* __restrict__ A, const float* __restrict__ Bt,
    const float* __restrict__ bias, float* __restrict__ C,
    int M, int N, int K)
{
    __shared__ uint32_t As[2][GA];
    __shared__ uint32_t Bs[2][GA];

    const int tid = threadIdx.x;
    const int wid = tid >> 5;
    const int lane = tid & 31;
    const int g   = lane >> 2;
    const int tig = lane & 3;
    const int lr15 = lane & 15;           // ldmatrix row offset
    const int lc4f = (lane >> 4) << 2;    // ldmatrix col offset (0 or 4)

    const int wr = wid >> 2;
    const int wc = wid & 3;

    const int brow = blockIdx.y * 128;
    const int bcol = blockIdx.x * 128;

    const int lrow = tid >> 2;
    const int lc4  = (tid & 3) * 4;

    const float* Ab = A + (size_t)brow * K;
    const float* Bb = Bt + (size_t)bcol * K;

    const uint32_t sA0 = smem_u32(&As[0][0]);
    const uint32_t sB0 = smem_u32(&Bs[0][0]);

    float acc[4][4][4];
    #pragma unroll
    for (int mi = 0; mi < 4; mi++)
        #pragma unroll
        for (int ni = 0; ni < 4; ni++)
            #pragma unroll
            for (int r = 0; r < 4; r++) acc[mi][ni][r] = 0.f;

    const int niter = K / 16;

    {
        float4 a0 = *(const float4*)(Ab + (size_t)lrow * K + lc4);
        float4 a1 = *(const float4*)(Ab + (size_t)(lrow + 64) * K + lc4);
        float4 b0 = *(const float4*)(Bb + (size_t)lrow * K + lc4);
        float4 b1 = *(const float4*)(Bb + (size_t)(lrow + 64) * K + lc4);
        *(uint4*)&As[0][lrow * PAD + lc4] =
            make_uint4(f2tf32(a0.x), f2tf32(a0.y), f2tf32(a0.z), f2tf32(a0.w));
        *(uint4*)&As[0][(lrow + 64) * PAD + lc4] =
            make_uint4(f2tf32(a1.x), f2tf32(a1.y), f2tf32(a1.z), f2tf32(a1.w));
        *(uint4*)&Bs[0][lrow * PAD + lc4] =
            make_uint4(f2tf32(b0.x), f2tf32(b0.y), f2tf32(b0.z), f2tf32(b0.w));
        *(uint4*)&Bs[0][(lrow + 64) * PAD + lc4] =
            make_uint4(f2tf32(b1.x), f2tf32(b1.y), f2tf32(b1.z), f2tf32(b1.w));
    }
    __syncthreads();

    for (int it = 0; it < niter; it++) {
        const int buf = it & 1;
        const bool has_next = (it + 1) < niter;

        float4 pa0, pa1, pb0, pb1;
        if (has_next) {
            const int k0 = (it + 1) * 16;
            pa0 = *(const float4*)(Ab + (size_t)lrow * K + k0 + lc4);
            pa1 = *(const float4*)(Ab + (size_t)(lrow + 64) * K + k0 + lc4);
            pb0 = *(const float4*)(Bb + (size_t)lrow * K + k0 + lc4);
            pb1 = *(const float4*)(Bb + (size_t)(lrow + 64) * K + k0 + lc4);
        }

        const uint32_t aBase = sA0 + buf * GA * 4;
        const uint32_t bBase = sB0 + buf * GA * 4;

        #pragma unroll
        for (int ks = 0; ks < 2; ks++) {
            const int kb = ks * 8;
            uint32_t af[4][4];
            uint32_t bf[4][2];
            #pragma unroll
            for (int mi = 0; mi < 4; mi++) {
                uint32_t addr = aBase +
                    (((wr * 64 + mi * 16 + lr15) * PAD) + kb + lc4f) * 4;
                ldsm_x4(af[mi][0], af[mi][1], af[mi][2], af[mi][3], addr);
            }
            #pragma unroll
            for (int p = 0; p < 2; p++) {
                uint32_t r0, r1, r2, r3;
                uint32_t addr = bBase +
                    (((wc * 32 + p * 16 + lr15) * PAD) + kb + lc4f) * 4;
                ldsm_x4(r0, r1, r2, r3, addr);
                bf[2 * p][0] = r0; bf[2 * p + 1][0] = r1;
                bf[2 * p][1] = r2; bf[2 * p + 1][1] = r3;
            }
            #pragma unroll
            for (int mi = 0; mi < 4; mi++)
                #pragma unroll
                for (int ni = 0; ni < 4; ni++)
                    mma_tf32_1688(acc[mi][ni][0], acc[mi][ni][1],
                                  acc[mi][ni][2], acc[mi][ni][3],
                                  af[mi][0], af[mi][1], af[mi][2], af[mi][3],
                                  bf[ni][0], bf[ni][1]);
        }

        if (has_next) {
            const int nbuf = buf ^ 1;
            *(uint4*)&As[nbuf][lrow * PAD + lc4] =
                make_uint4(f2tf32(pa0.x), f2tf32(pa0.y), f2tf32(pa0.z), f2tf32(pa0.w));
            *(uint4*)&As[nbuf][(lrow + 64) * PAD + lc4] =
                make_uint4(f2tf32(pa1.x), f2tf32(pa1.y), f2tf32(pa1.z), f2tf32(pa1.w));
            *(uint4*)&Bs[nbuf][lrow * PAD + lc4] =
                make_uint4(f2tf32(pb0.x), f2tf32(pb0.y), f2tf32(pb0.z), f2tf32(pb0.w));
            *(uint4*)&Bs[nbuf][(lrow + 64) * PAD + lc4] =
                make_uint4(f2tf32(pb1.x), f2tf32(pb1.y), f2tf32(pb1.z), f2tf32(pb1.w));
        }
        __syncthreads();
    }

    #pragma unroll
    for (int mi = 0; mi < 4; mi++) {
        const int row0 = brow + wr * 64 + mi * 16 + g;
        #pragma unroll
        for (int ni = 0; ni < 4; ni++) {
            const int col0 = bcol + wc * 32 + ni * 8 + 2 * tig;
            const float bx = bias[col0], by = bias[col0 + 1];
            float2 lo = make_float2(acc[mi][ni][0] + bx, acc[mi][ni][1] + by);
            float2 hi = make_float2(acc[mi][ni][2] + bx, acc[mi][ni][3] + by);
            *(float2*)(C + (size_t)row0 * N + col0) = lo;
            *(float2*)(C + (size_t)(row0 + 8) * N + col0) = hi;
        }
    }
}

// ---------------------------------------------------------------------------
// 32x32 tiled transpose
// ---------------------------------------------------------------------------
__global__ void transpose_kernel(const float* __restrict__ W, float* __restrict__ Wt,
                                 int R, int Ccols)
{
    __shared__ float t[32][33];
    int bx = blockIdx.x * 32, by = blockIdx.y * 32;
    int x = bx + threadIdx.x;
    #pragma unroll
    for (int j = 0; j < 32; j += 8)
        t[threadIdx.y + j][threadIdx.x] = W[(size_t)(by + threadIdx.y + j) * Ccols + x];
    __syncthreads();
    int xo = by + threadIdx.x;
    #pragma unroll
    for (int j = 0; j < 32; j += 8)
        Wt[(size_t)(bx + threadIdx.y + j) * R + xo] = t[threadIdx.x][threadIdx.y + j];
}

// ---------------------------------------------------------------------------
// Causal flash attention on tf32 mma.sync + ldmatrix fragment loads.
// Smem (u32): Ks[64][68] K-major; Vt[64][72] = V^T [d][key] with 4-granule
// swizzle (key&~3)^(((d>>2)&3)<<2); Ss[128][68] Q staging then P strips.
// ---------------------------------------------------------------------------
#define AT_PAD 68
#define AT_PADV 72
#define AT_KS 0
#define AT_VT (64 * AT_PAD)                    // 4352
#define AT_SS (AT_VT + 64 * AT_PADV)           // 8960
#define ATTN_SMEM ((AT_SS + 128 * AT_PAD) * 4) // 70656 bytes

__global__ __launch_bounds__(256) void attn_mma_kernel(
    const float* __restrict__ qkv, float* __restrict__ out)
{
    extern __shared__ uint32_t sm[];
    uint32_t* Ks = sm + AT_KS;
    uint32_t* Vt = sm + AT_VT;
    uint32_t* Ss = sm + AT_SS;

    const int tid = threadIdx.x;
    const int wid = tid >> 5;
    const int lane = tid & 31;
    const int g = lane >> 2;
    const int tig = lane & 3;
    const int lr15 = lane & 15;
    const int lc4f = (lane >> 4) << 2;
    const int q0 = blockIdx.x * 128;
    const int h = blockIdx.y;
    const int b = blockIdx.z;

    const uint32_t sbase = smem_u32(sm);
    const uint32_t ksU = sbase + AT_KS * 4;
    const uint32_t vtU = sbase + AT_VT * 4;
    const uint32_t psU = sbase + (AT_SS + (wid * 16) * AT_PAD) * 4;

    const size_t rs = C3;
    const float* qbase = qkv + (size_t)b * TT * rs + h * DD;
    const float* kbase = qbase + CC;
    const float* vbase = qbase + 2 * CC;

    const int lrow = tid >> 4;        // 0..15
    const int lc4  = (tid & 15) * 4;  // 0..60

    // ---- Stage Q tile (128x64) into Ss as tf32, build A-fragments in regs
    #pragma unroll
    for (int r = 0; r < 8; r++) {
        int row = r * 16 + lrow;
        float4 v = *(const float4*)(qbase + (size_t)(q0 + row) * rs + lc4);
        uint32_t* d = &Ss[row * AT_PAD + lc4];
        d[0] = f2tf32(v.x); d[1] = f2tf32(v.y);
        d[2] = f2tf32(v.z); d[3] = f2tf32(v.w);
    }
    __syncthreads();

    uint32_t qf[8][4];
    #pragma unroll
    for (int ks = 0; ks < 8; ks++) {
        ldsm_x4(qf[ks][0], qf[ks][1], qf[ks][2], qf[ks][3],
                psU + (lr15 * AT_PAD + ks * 8 + lc4f) * 4);
    }
    __syncthreads();   // Ss now free for P strips

    float of[8][4];
    #pragma unroll
    for (int nf = 0; nf < 8; nf++)
        #pragma unroll
        for (int r = 0; r < 4; r++) of[nf][r] = 0.f;

    float m_lo = -1e30f, m_hi = -1e30f, l_lo = 0.f, l_hi = 0.f;
    const float sc = 0.125f * 1.44269504088896f;   // scale * log2(e)
    const int nt = q0 / 64 + 2;
    const int qlo = q0 + wid * 16 + g;
    const int qhi = qlo + 8;
    const int swzL = ((lr15 >> 2) & 3) << 2;   // Vt granule swizzle (per lane)

    uint32_t* ps = &Ss[(wid * 16) * AT_PAD];   // this warp's P strip (generic)

    for (int t = 0; t < nt; t++) {
        const int k0 = t * 64;

        // ---- load K tile (K-major) and V tile (transposed, granule-swizzled)
        #pragma unroll
        for (int r = 0; r < 4; r++) {
            int row = r * 16 + lrow;   // key index 0..63
            float4 kv = *(const float4*)(kbase + (size_t)(k0 + row) * rs + lc4);
            uint32_t* kd = &Ks[row * AT_PAD + lc4];
            kd[0] = f2tf32(kv.x); kd[1] = f2tf32(kv.y);
            kd[2] = f2tf32(kv.z); kd[3] = f2tf32(kv.w);
            float4 vv = *(const float4*)(vbase + (size_t)(k0 + row) * rs + lc4);
            float vs[4] = {vv.x, vv.y, vv.z, vv.w};
            int rlo = row & 3, rhb = row & ~3;
            #pragma unroll
            for (int i = 0; i < 4; i++) {
                int d = lc4 + i;
                int swz = ((d >> 2) & 3) << 2;
                Vt[d * AT_PADV + ((rhb ^ swz) | rlo)] = f2tf32(vs[i]);
            }
        }
        __syncthreads();

        const bool skip = (t == nt - 1) && (wid < 4);
        if (!skip) {
            // ---- S = Q @ K^T  (16q x 64k per warp)
            float sf[8][4];
            #pragma unroll
            for (int nf = 0; nf < 8; nf++)
                #pragma unroll
                for (int r = 0; r < 4; r++) sf[nf][r] = 0.f;

            #pragma unroll
            for (int ks = 0; ks < 8; ks++) {
                uint32_t bq[8][2];
                #pragma unroll
                for (int p = 0; p < 4; p++) {
                    uint32_t r0, r1, r2, r3;
                    ldsm_x4(r0, r1, r2, r3,
                            ksU + ((p * 16 + lr15) * AT_PAD + ks * 8 + lc4f) * 4);
                    bq[2 * p][0] = r0; bq[2 * p + 1][0] = r1;
                    bq[2 * p][1] = r2; bq[2 * p + 1][1] = r3;
                }
                #pragma unroll
                for (int nf = 0; nf < 8; nf++)
                    mma_tf32_1688(sf[nf][0], sf[nf][1], sf[nf][2], sf[nf][3],
                                  qf[ks][0], qf[ks][1], qf[ks][2], qf[ks][3],
                                  bq[nf][0], bq[nf][1]);
            }

            // ---- scale + causal mask + tile max
            const bool diag = (t == nt - 1) || (t == nt - 2 && wid < 4);
            float tmax_lo = -1e30f, tmax_hi = -1e30f;
            #pragma unroll
            for (int nf = 0; nf < 8; nf++) {
                int kg = k0 + nf * 8 + 2 * tig;
                float s0 = sf[nf][0] * sc, s1 = sf[nf][1] * sc;
                float s2 = sf[nf][2] * sc, s3 = sf[nf][3] * sc;
                if (diag) {
                    if (kg     > qlo) s0 = -1e30f;
                    if (kg + 1 > qlo) s1 = -1e30f;
                    if (kg     > qhi) s2 = -1e30f;
                    if (kg + 1 > qhi) s3 = -1e30f;
                }
                sf[nf][0] = s0; sf[nf][1] = s1; sf[nf][2] = s2; sf[nf][3] = s3;
                tmax_lo = fmaxf(tmax_lo, fmaxf(s0, s1));
                tmax_hi = fmaxf(tmax_hi, fmaxf(s2, s3));
            }
            tmax_lo = fmaxf(tmax_lo, __shfl_xor_sync(0xFFFFFFFFu, tmax_lo, 1));
            tmax_lo = fmaxf(tmax_lo, __shfl_xor_sync(0xFFFFFFFFu, tmax_lo, 2));
            tmax_hi = fmaxf(tmax_hi, __shfl_xor_sync(0xFFFFFFFFu, tmax_hi, 1));
            tmax_hi = fmaxf(tmax_hi, __shfl_xor_sync(0xFFFFFFFFu, tmax_hi, 2));

            const float mn_lo = fmaxf(m_lo, tmax_lo);
            const float mn_hi = fmaxf(m_hi, tmax_hi);
            const float corr_lo = exp2f(m_lo - mn_lo);
            const float corr_hi = exp2f(m_hi - mn_hi);
            m_lo = mn_lo; m_hi = mn_hi;
            l_lo *= corr_lo; l_hi *= corr_hi;
            #pragma unroll
            for (int nf = 0; nf < 8; nf++) {
                of[nf][0] *= corr_lo; of[nf][1] *= corr_lo;
                of[nf][2] *= corr_hi; of[nf][3] *= corr_hi;
            }

            // ---- P = exp2(S - m); store tf32 P strip; accumulate l
            #pragma unroll
            for (int nf = 0; nf < 8; nf++) {
                float p0 = exp2f(sf[nf][0] - mn_lo);
                float p1 = exp2f(sf[nf][1] - mn_lo);
                float p2 = exp2f(sf[nf][2] - mn_hi);
                float p3 = exp2f(sf[nf][3] - mn_hi);
                l_lo += p0 + p1;
                l_hi += p2 + p3;
                uint2 plo = make_uint2(f2tf32(p0), f2tf32(p1));
                uint2 phi = make_uint2(f2tf32(p2), f2tf32(p3));
                *(uint2*)&ps[g * AT_PAD + nf * 8 + 2 * tig] = plo;
                *(uint2*)&ps[(g + 8) * AT_PAD + nf * 8 + 2 * tig] = phi;
            }
            __syncwarp();

            // ---- O += P @ V   (P via LDSM from strip, V^T via LDSM from Vt)
            #pragma unroll
            for (int ks = 0; ks < 8; ks++) {
                uint32_t a0, a1, a2, a3;
                ldsm_x4(a0, a1, a2, a3,
                        psU + (lr15 * AT_PAD + ks * 8 + lc4f) * 4);
                #pragma unroll
                for (int p = 0; p < 4; p++) {
                    uint32_t r0, r1, r2, r3;
                    ldsm_x4(r0, r1, r2, r3,
                            vtU + ((p * 16 + lr15) * AT_PADV +
                                   ((ks * 8 + lc4f) ^ swzL)) * 4);
                    mma_tf32_1688(of[2 * p][0], of[2 * p][1],
                                  of[2 * p][2], of[2 * p][3],
                                  a0, a1, a2, a3, r0, r2);
                    mma_tf32_1688(of[2 * p + 1][0], of[2 * p + 1][1],
                                  of[2 * p + 1][2], of[2 * p + 1][3],
                                  a0, a1, a2, a3, r1, r3);
                }
            }
        }
        __syncthreads();
    }

    // ---- finalize: quad-reduce l, divide, write out [B,T,H,D]
    l_lo += __shfl_xor_sync(0xFFFFFFFFu, l_lo, 1);
    l_lo += __shfl_xor_sync(0xFFFFFFFFu, l_lo, 2);
    l_hi += __shfl_xor_sync(0xFFFFFFFFu, l_hi, 1);
    l_hi += __shfl_xor_sync(0xFFFFFFFFu, l_hi, 2);
    const float inv_lo = 1.f / l_lo;
    const float inv_hi = 1.f / l_hi;

    float* olo = out + ((size_t)b * TT + qlo) * CC + h * DD;
    float* ohi = out + ((size_t)b * TT + qhi) * CC + h * DD;
    #pragma unroll
    for (int nf = 0; nf < 8; nf++) {
        float2 lo = make_float2(of[nf][0] * inv_lo, of[nf][1] * inv_lo);
        float2 hi = make_float2(of[nf][2] * inv_hi, of[nf][3] * inv_hi);
        *(float2*)(olo + nf * 8 + 2 * tig) = lo;
        *(float2*)(ohi + nf * 8 + 2 * tig) = hi;
    }
}

// ---------------------------------------------------------------------------
// Launch
// ---------------------------------------------------------------------------
extern "C" void kernel_launch(void* const* d_in, const int* in_sizes, int n_in,
                              void* d_out, int out_size)
{
    const float* x     = (const float*)d_in[0];
    const float* W_qkv = (const float*)d_in[1];
    const float* b_qkv = (const float*)d_in[2];
    const float* W_out = (const float*)d_in[3];
    const float* b_out = (const float*)d_in[4];
    float* out = (float*)d_out;

    float *qkv = nullptr, *attn = nullptr, *wqkv_t = nullptr, *wout_t = nullptr;
    cudaGetSymbolAddress((void**)&qkv,    g_qkv);
    cudaGetSymbolAddress((void**)&attn,   g_attn);
    cudaGetSymbolAddress((void**)&wqkv_t, g_wqkv_t);
    cudaGetSymbolAddress((void**)&wout_t, g_wout_t);

    cudaFuncSetAttribute(attn_mma_kernel,
                         cudaFuncAttributeMaxDynamicSharedMemorySize, ATTN_SMEM);

    // 0) Transpose weights to K-major
    {
        dim3 blk(32, 8);
        transpose_kernel<<<dim3(C3 / 32, CC / 32), blk>>>(W_qkv, wqkv_t, CC, C3);
        transpose_kernel<<<dim3(CC / 32, CC / 32), blk>>>(W_out, wout_t, CC, CC);
    }

    // 1) QKV projection (tf32 mma.sync + ldmatrix, 128x128 blocks)
    {
        dim3 grid(C3 / 128, MROWS / 128);
        gemm_mma_tf32<<<grid, 256>>>(x, wqkv_t, b_qkv, qkv, MROWS, C3, CC);
    }

    // 2) Causal attention (tf32 mma.sync + ldmatrix flash attention)
    {
        dim3 grid(TT / 128, HH, BB);
        attn_mma_kernel<<<grid, 256, ATTN_SMEM>>>(qkv, attn);
    }

    // 3) Output projection (tf32 mma.sync + ldmatrix, 128x128 blocks)
    {
        dim3 grid(CC / 128, MROWS / 128);
        gemm_mma_tf32<<<grid, 256>>>(attn, wout_t, b_out, out, MROWS, CC, CC);
    }
}